// round 1
// baseline (speedup 1.0000x reference)
#include <cuda_runtime.h>
#include <math.h>

#define Dm 2048
#define Hn 16
#define Dh 128
#define Bb 2
#define Ll 2048
#define Mm (Bb*Ll)   /* 4096 rows */

// ---------------- scratch (static device globals; no runtime allocation) ----
__device__ float g_Q[(size_t)Mm * Dm];
__device__ float g_K[(size_t)Mm * Dm];
__device__ float g_V[(size_t)Mm * Dm];
__device__ float g_O[(size_t)Mm * Dm];
__device__ float g_invf[Dh/2];

// ---------------- inv_freq table (64 threads, double pow for exactness) -----
__global__ void invf_kernel() {
    int i = threadIdx.x;
    if (i < Dh/2)
        g_invf[i] = (float)pow(10000.0, -(double)(2*i) / (double)Dh);
}

// ---------------- SGEMM: C[M,N] = A[M,K] * W[N,K]^T  (NT, fp32) -------------
// BM=BN=128, BK=8, 256 threads, 8x8 micro-tile, register prefetch.
__global__ void __launch_bounds__(256, 2)
sgemm_nt(const float* __restrict__ A, const float* __restrict__ W,
         float* __restrict__ C, int Kdim, int Ndim)
{
    __shared__ float As[8][128];
    __shared__ float Bs[8][128];
    const int tid = threadIdx.x;
    const int tx = tid & 15, ty = tid >> 4;
    const int row0 = blockIdx.y << 7;
    const int col0 = blockIdx.x << 7;

    const int lr = tid >> 1;          // 0..127
    const int lk = (tid & 1) << 2;    // 0 or 4
    const float* Ap = A + (size_t)(row0 + lr) * Kdim + lk;
    const float* Wp = W + (size_t)(col0 + lr) * Kdim + lk;

    float acc[8][8];
#pragma unroll
    for (int i = 0; i < 8; i++)
#pragma unroll
        for (int j = 0; j < 8; j++) acc[i][j] = 0.f;

    float4 a4 = *(const float4*)Ap;
    float4 b4 = *(const float4*)Wp;

    for (int k0 = 0; k0 < Kdim; k0 += 8) {
        As[lk+0][lr] = a4.x; As[lk+1][lr] = a4.y; As[lk+2][lr] = a4.z; As[lk+3][lr] = a4.w;
        Bs[lk+0][lr] = b4.x; Bs[lk+1][lr] = b4.y; Bs[lk+2][lr] = b4.z; Bs[lk+3][lr] = b4.w;
        __syncthreads();
        if (k0 + 8 < Kdim) {
            a4 = *(const float4*)(Ap + k0 + 8);
            b4 = *(const float4*)(Wp + k0 + 8);
        }
#pragma unroll
        for (int kk = 0; kk < 8; kk++) {
            float ar[8], br[8];
            *(float4*)&ar[0] = *(const float4*)&As[kk][ty*8];
            *(float4*)&ar[4] = *(const float4*)&As[kk][ty*8+4];
            *(float4*)&br[0] = *(const float4*)&Bs[kk][tx*8];
            *(float4*)&br[4] = *(const float4*)&Bs[kk][tx*8+4];
#pragma unroll
            for (int i = 0; i < 8; i++)
#pragma unroll
                for (int j = 0; j < 8; j++)
                    acc[i][j] = fmaf(ar[i], br[j], acc[i][j]);
        }
        __syncthreads();
    }

#pragma unroll
    for (int i = 0; i < 8; i++) {
        float* cp = C + (size_t)(row0 + ty*8 + i) * Ndim + col0 + tx*8;
        *(float4*)cp     = make_float4(acc[i][0], acc[i][1], acc[i][2], acc[i][3]);
        *(float4*)(cp+4) = make_float4(acc[i][4], acc[i][5], acc[i][6], acc[i][7]);
    }
}

// ---------------- RoPE (in-place on Q and K) ---------------------------------
__global__ void rope_kernel(const int* __restrict__ pos,
                            float* __restrict__ Q, float* __restrict__ K)
{
    int idx = blockIdx.x * blockDim.x + threadIdx.x;    // over B*L*H*(Dh/2) = 2^22
    int i = idx & 63;
    int h = (idx >> 6) & 15;
    int l = (idx >> 10) & (Ll - 1);
    int b = idx >> 21;

    int p = pos[b * Ll + l];
    float ph = (float)p * g_invf[i];
    float s, c;
    sincosf(ph, &s, &c);

    size_t base = ((size_t)(b * Ll + l)) * Dm + h * Dh + 2 * i;
    float q1 = Q[base], q2 = Q[base + 1];
    Q[base]     = q1 * c - q2 * s;
    Q[base + 1] = q1 * s + q2 * c;
    float k1 = K[base], k2 = K[base + 1];
    K[base]     = k1 * c - k2 * s;
    K[base + 1] = k1 * s + k2 * c;
}

// ---------------- fused causal flash attention (fp32) ------------------------
// Block = (b, h, q-tile of 64 rows). 256 threads. dh=128 fully in shared.
// Q,K tiles stored k-major [128][64] with XOR swizzle -> conflict-free float4
// loads in the S-GEMM hot loop. V row-major [64][128]. S in [64][68].
#define ATT_SMEM_FLOATS (8192*3 + 64*68 + 192)

__global__ void __launch_bounds__(256, 1)
attn_kernel(const float* __restrict__ Q, const float* __restrict__ Kg,
            const float* __restrict__ V, float* __restrict__ O)
{
    extern __shared__ float sm[];
    float* Qt  = sm;             // [128][64] swizzled, k-major
    float* Kt  = sm + 8192;
    float* Vs  = sm + 16384;     // [64][128]
    float* Ss  = sm + 24576;     // [64][68]
    float* m_s = Ss + 64*68;
    float* l_s = m_s + 64;
    float* a_s = l_s + 64;

    const int tid  = threadIdx.x;
    const int lane = tid & 31, wid = tid >> 5;
    const int tx = tid & 15, ty = tid >> 4;
    const int qt = (int)(gridDim.x - 1 - blockIdx.x);  // heavy tiles first
    const int h  = blockIdx.y, b = blockIdx.z;
    const int qi0 = qt * 64;
    const size_t rowbase = (size_t)b * Ll;
    const int hoff = h * Dh;
    const float NEG = -1e30f;
    const float SCALE = 0.08838834764831845f;  // 1/sqrt(128)

    // load Q tile -> Qt (transposed + swizzled)
#pragma unroll
    for (int it = 0; it < 8; it++) {
        int r  = wid + 8 * it;
        int kq = lane << 2;
        float4 v = *(const float4*)(Q + (rowbase + qi0 + r) * Dm + hoff + kq);
        int g = r >> 2, rb = r & 3;
        const float* vp = (const float*)&v;
#pragma unroll
        for (int c = 0; c < 4; c++) {
            int k = kq + c;
            Qt[k*64 + (((g ^ (k >> 2)) & 15) << 2) + rb] = vp[c];
        }
    }
    if (tid < 64) { m_s[tid] = __int_as_float(0xff800000); l_s[tid] = 0.f; }

    float oacc[4][8];
#pragma unroll
    for (int i = 0; i < 4; i++)
#pragma unroll
        for (int j = 0; j < 8; j++) oacc[i][j] = 0.f;

    for (int kt = 0; kt <= qt; kt++) {
        const int kj0 = kt * 64;
        __syncthreads();
        // load K (swizzled k-major) and V (row-major)
#pragma unroll
        for (int it = 0; it < 8; it++) {
            int r  = wid + 8 * it;
            int kq = lane << 2;
            float4 kv = *(const float4*)(Kg + (rowbase + kj0 + r) * Dm + hoff + kq);
            int g = r >> 2, rb = r & 3;
            const float* kp = (const float*)&kv;
#pragma unroll
            for (int c = 0; c < 4; c++) {
                int k = kq + c;
                Kt[k*64 + (((g ^ (k >> 2)) & 15) << 2) + rb] = kp[c];
            }
            float4 vv = *(const float4*)(V + (rowbase + kj0 + r) * Dm + hoff + kq);
            *(float4*)&Vs[r*128 + kq] = vv;
        }
        __syncthreads();

        // S = Q K^T  (4x4 micro-tile per thread)
        float sacc[4][4];
#pragma unroll
        for (int i = 0; i < 4; i++)
#pragma unroll
            for (int j = 0; j < 4; j++) sacc[i][j] = 0.f;

#pragma unroll 8
        for (int k = 0; k < 128; k++) {
            int sw = (k >> 2) & 15;
            float4 aq = *(const float4*)&Qt[k*64 + ((ty ^ sw) << 2)];
            float4 bk = *(const float4*)&Kt[k*64 + ((tx ^ sw) << 2)];
            const float* ap = (const float*)&aq;
            const float* bp = (const float*)&bk;
#pragma unroll
            for (int i = 0; i < 4; i++)
#pragma unroll
                for (int j = 0; j < 4; j++)
                    sacc[i][j] = fmaf(ap[i], bp[j], sacc[i][j]);
        }
        const bool diag = (kt == qt);
#pragma unroll
        for (int i = 0; i < 4; i++)
#pragma unroll
            for (int j = 0; j < 4; j++) {
                float v = sacc[i][j] * SCALE;
                if (diag && (tx*4 + j) > (ty*4 + i)) v = NEG;
                Ss[(ty*4 + i)*68 + tx*4 + j] = v;
            }
        __syncthreads();

        // online softmax (4 threads per row)
        {
            int r = tid >> 2, sg = tid & 3;
            float* row = Ss + r*68 + sg*16;
            float mo = m_s[r];
            float mx = NEG;
#pragma unroll
            for (int c = 0; c < 16; c++) mx = fmaxf(mx, row[c]);
            mx = fmaxf(mx, __shfl_xor_sync(0xffffffffu, mx, 1));
            mx = fmaxf(mx, __shfl_xor_sync(0xffffffffu, mx, 2));
            float mn = fmaxf(mo, mx);
            float alpha = expf(mo - mn);
            float sum = 0.f;
#pragma unroll
            for (int c = 0; c < 16; c++) {
                float p = expf(row[c] - mn);
                row[c] = p;
                sum += p;
            }
            sum += __shfl_xor_sync(0xffffffffu, sum, 1);
            sum += __shfl_xor_sync(0xffffffffu, sum, 2);
            if (sg == 0) {
                m_s[r] = mn;
                l_s[r] = l_s[r] * alpha + sum;
                a_s[r] = alpha;
            }
        }
        __syncthreads();

        // rescale O, accumulate P*V
#pragma unroll
        for (int i = 0; i < 4; i++) {
            float al = a_s[ty*4 + i];
#pragma unroll
            for (int j = 0; j < 8; j++) oacc[i][j] *= al;
        }
#pragma unroll 4
        for (int j = 0; j < 64; j++) {
            float p0 = Ss[(ty*4 + 0)*68 + j];
            float p1 = Ss[(ty*4 + 1)*68 + j];
            float p2 = Ss[(ty*4 + 2)*68 + j];
            float p3 = Ss[(ty*4 + 3)*68 + j];
            float4 v0 = *(const float4*)&Vs[j*128 + tx*8];
            float4 v1 = *(const float4*)&Vs[j*128 + tx*8 + 4];
            const float* va = (const float*)&v0;
            const float* vb = (const float*)&v1;
#pragma unroll
            for (int c = 0; c < 4; c++) {
                oacc[0][c]   = fmaf(p0, va[c], oacc[0][c]);
                oacc[1][c]   = fmaf(p1, va[c], oacc[1][c]);
                oacc[2][c]   = fmaf(p2, va[c], oacc[2][c]);
                oacc[3][c]   = fmaf(p3, va[c], oacc[3][c]);
                oacc[0][4+c] = fmaf(p0, vb[c], oacc[0][4+c]);
                oacc[1][4+c] = fmaf(p1, vb[c], oacc[1][4+c]);
                oacc[2][4+c] = fmaf(p2, vb[c], oacc[2][4+c]);
                oacc[3][4+c] = fmaf(p3, vb[c], oacc[3][4+c]);
            }
        }
    }

    // epilogue: O / l, write
#pragma unroll
    for (int i = 0; i < 4; i++) {
        float inv = 1.f / l_s[ty*4 + i];
        float* op = O + (rowbase + qi0 + ty*4 + i) * Dm + hoff + tx*8;
        *(float4*)op     = make_float4(oacc[i][0]*inv, oacc[i][1]*inv,
                                       oacc[i][2]*inv, oacc[i][3]*inv);
        *(float4*)(op+4) = make_float4(oacc[i][4]*inv, oacc[i][5]*inv,
                                       oacc[i][6]*inv, oacc[i][7]*inv);
    }
}

// ---------------- launch ------------------------------------------------------
extern "C" void kernel_launch(void* const* d_in, const int* in_sizes, int n_in,
                              void* d_out, int out_size)
{
    const float* x  = (const float*)d_in[0];
    const int*  pos = (const int*)d_in[1];
    const float* Wq = (const float*)d_in[2];
    const float* Wk = (const float*)d_in[3];
    const float* Wv = (const float*)d_in[4];
    const float* Wo = (const float*)d_in[5];
    float* out = (float*)d_out;

    float *qp, *kp, *vp, *op;
    cudaGetSymbolAddress((void**)&qp, g_Q);
    cudaGetSymbolAddress((void**)&kp, g_K);
    cudaGetSymbolAddress((void**)&vp, g_V);
    cudaGetSymbolAddress((void**)&op, g_O);

    invf_kernel<<<1, 64>>>();

    dim3 gblk(Dm/128, Mm/128);   // (16, 32)
    sgemm_nt<<<gblk, 256>>>(x, Wq, qp, Dm, Dm);
    sgemm_nt<<<gblk, 256>>>(x, Wk, kp, Dm, Dm);
    sgemm_nt<<<gblk, 256>>>(x, Wv, vp, Dm, Dm);

    int npairs = Bb * Ll * Hn * (Dh/2);
    rope_kernel<<<npairs/256, 256>>>(pos, qp, kp);

    cudaFuncSetAttribute(attn_kernel,
                         cudaFuncAttributeMaxDynamicSharedMemorySize,
                         ATT_SMEM_FLOATS * (int)sizeof(float));
    dim3 agrid(Ll/64, Hn, Bb);
    attn_kernel<<<agrid, 256, ATT_SMEM_FLOATS * (int)sizeof(float)>>>(qp, kp, vp, op);

    sgemm_nt<<<gblk, 256>>>(op, Wo, out, Dm, Dm);
}

// round 2
// speedup vs baseline: 1.0000x; 1.0000x over previous
#include <cuda_runtime.h>
#include <math.h>

#define Dm 2048
#define Hn 16
#define Dh 128
#define Bb 2
#define Ll 2048
#define Mm (Bb*Ll)   /* 4096 rows */

// ---------------- scratch (static device globals; no runtime allocation) ----
__device__ float g_Q[(size_t)Mm * Dm];
__device__ float g_K[(size_t)Mm * Dm];
__device__ float g_V[(size_t)Mm * Dm];
__device__ float g_O[(size_t)Mm * Dm];
__device__ float g_invf[Dh/2];

// ---------------- inv_freq table (64 threads, double pow for exactness) -----
__global__ void invf_kernel() {
    int i = threadIdx.x;
    if (i < Dh/2)
        g_invf[i] = (float)pow(10000.0, -(double)(2*i) / (double)Dh);
}

// ---------------- SGEMM: C[M,N] = A[M,K] * W[N,K]^T  (NT, fp32) -------------
// BM=BN=128, BK=8, 256 threads, 8x8 micro-tile, register prefetch.
__global__ void __launch_bounds__(256, 2)
sgemm_nt(const float* __restrict__ A, const float* __restrict__ W,
         float* __restrict__ C, int Kdim, int Ndim)
{
    __shared__ float As[8][128];
    __shared__ float Bs[8][128];
    const int tid = threadIdx.x;
    const int tx = tid & 15, ty = tid >> 4;
    const int row0 = blockIdx.y << 7;
    const int col0 = blockIdx.x << 7;

    const int lr = tid >> 1;          // 0..127
    const int lk = (tid & 1) << 2;    // 0 or 4
    const float* Ap = A + (size_t)(row0 + lr) * Kdim + lk;
    const float* Wp = W + (size_t)(col0 + lr) * Kdim + lk;

    float acc[8][8];
#pragma unroll
    for (int i = 0; i < 8; i++)
#pragma unroll
        for (int j = 0; j < 8; j++) acc[i][j] = 0.f;

    float4 a4 = *(const float4*)Ap;
    float4 b4 = *(const float4*)Wp;

    for (int k0 = 0; k0 < Kdim; k0 += 8) {
        As[lk+0][lr] = a4.x; As[lk+1][lr] = a4.y; As[lk+2][lr] = a4.z; As[lk+3][lr] = a4.w;
        Bs[lk+0][lr] = b4.x; Bs[lk+1][lr] = b4.y; Bs[lk+2][lr] = b4.z; Bs[lk+3][lr] = b4.w;
        __syncthreads();
        if (k0 + 8 < Kdim) {
            a4 = *(const float4*)(Ap + k0 + 8);
            b4 = *(const float4*)(Wp + k0 + 8);
        }
#pragma unroll
        for (int kk = 0; kk < 8; kk++) {
            float ar[8], br[8];
            *(float4*)&ar[0] = *(const float4*)&As[kk][ty*8];
            *(float4*)&ar[4] = *(const float4*)&As[kk][ty*8+4];
            *(float4*)&br[0] = *(const float4*)&Bs[kk][tx*8];
            *(float4*)&br[4] = *(const float4*)&Bs[kk][tx*8+4];
#pragma unroll
            for (int i = 0; i < 8; i++)
#pragma unroll
                for (int j = 0; j < 8; j++)
                    acc[i][j] = fmaf(ar[i], br[j], acc[i][j]);
        }
        __syncthreads();
    }

#pragma unroll
    for (int i = 0; i < 8; i++) {
        float* cp = C + (size_t)(row0 + ty*8 + i) * Ndim + col0 + tx*8;
        *(float4*)cp     = make_float4(acc[i][0], acc[i][1], acc[i][2], acc[i][3]);
        *(float4*)(cp+4) = make_float4(acc[i][4], acc[i][5], acc[i][6], acc[i][7]);
    }
}

// ---------------- RoPE (in-place on Q and K) ---------------------------------
__global__ void rope_kernel(const int* __restrict__ pos,
                            float* __restrict__ Q, float* __restrict__ K)
{
    int idx = blockIdx.x * blockDim.x + threadIdx.x;    // over B*L*H*(Dh/2) = 2^22
    int i = idx & 63;
    int h = (idx >> 6) & 15;
    int l = (idx >> 10) & (Ll - 1);
    int b = idx >> 21;

    int p = pos[b * Ll + l];
    float ph = (float)p * g_invf[i];
    float s, c;
    sincosf(ph, &s, &c);

    size_t base = ((size_t)(b * Ll + l)) * Dm + h * Dh + 2 * i;
    float q1 = Q[base], q2 = Q[base + 1];
    Q[base]     = q1 * c - q2 * s;
    Q[base + 1] = q1 * s + q2 * c;
    float k1 = K[base], k2 = K[base + 1];
    K[base]     = k1 * c - k2 * s;
    K[base + 1] = k1 * s + k2 * c;
}

// ---------------- fused causal flash attention (fp32) ------------------------
// Block = (b, h, q-tile of 64 rows). 256 threads. dh=128 fully in shared.
// Q,K tiles stored k-major [128][64] with XOR swizzle -> conflict-free float4
// loads in the S-GEMM hot loop. V row-major [64][128]. S in [64][68].
#define ATT_SMEM_FLOATS (8192*3 + 64*68 + 192)

__global__ void __launch_bounds__(256, 1)
attn_kernel(const float* __restrict__ Q, const float* __restrict__ Kg,
            const float* __restrict__ V, float* __restrict__ O)
{
    extern __shared__ float sm[];
    float* Qt  = sm;             // [128][64] swizzled, k-major
    float* Kt  = sm + 8192;
    float* Vs  = sm + 16384;     // [64][128]
    float* Ss  = sm + 24576;     // [64][68]
    float* m_s = Ss + 64*68;
    float* l_s = m_s + 64;
    float* a_s = l_s + 64;

    const int tid  = threadIdx.x;
    const int lane = tid & 31, wid = tid >> 5;
    const int tx = tid & 15, ty = tid >> 4;
    const int qt = (int)(gridDim.x - 1 - blockIdx.x);  // heavy tiles first
    const int h  = blockIdx.y, b = blockIdx.z;
    const int qi0 = qt * 64;
    const size_t rowbase = (size_t)b * Ll;
    const int hoff = h * Dh;
    const float NEG = -1e30f;
    const float SCALE = 0.08838834764831845f;  // 1/sqrt(128)

    // load Q tile -> Qt (transposed + swizzled)
#pragma unroll
    for (int it = 0; it < 8; it++) {
        int r  = wid + 8 * it;
        int kq = lane << 2;
        float4 v = *(const float4*)(Q + (rowbase + qi0 + r) * Dm + hoff + kq);
        int g = r >> 2, rb = r & 3;
        const float* vp = (const float*)&v;
#pragma unroll
        for (int c = 0; c < 4; c++) {
            int k = kq + c;
            Qt[k*64 + (((g ^ (k >> 2)) & 15) << 2) + rb] = vp[c];
        }
    }
    if (tid < 64) { m_s[tid] = __int_as_float(0xff800000); l_s[tid] = 0.f; }

    float oacc[4][8];
#pragma unroll
    for (int i = 0; i < 4; i++)
#pragma unroll
        for (int j = 0; j < 8; j++) oacc[i][j] = 0.f;

    for (int kt = 0; kt <= qt; kt++) {
        const int kj0 = kt * 64;
        __syncthreads();
        // load K (swizzled k-major) and V (row-major)
#pragma unroll
        for (int it = 0; it < 8; it++) {
            int r  = wid + 8 * it;
            int kq = lane << 2;
            float4 kv = *(const float4*)(Kg + (rowbase + kj0 + r) * Dm + hoff + kq);
            int g = r >> 2, rb = r & 3;
            const float* kp = (const float*)&kv;
#pragma unroll
            for (int c = 0; c < 4; c++) {
                int k = kq + c;
                Kt[k*64 + (((g ^ (k >> 2)) & 15) << 2) + rb] = kp[c];
            }
            float4 vv = *(const float4*)(V + (rowbase + kj0 + r) * Dm + hoff + kq);
            *(float4*)&Vs[r*128 + kq] = vv;
        }
        __syncthreads();

        // S = Q K^T  (4x4 micro-tile per thread)
        float sacc[4][4];
#pragma unroll
        for (int i = 0; i < 4; i++)
#pragma unroll
            for (int j = 0; j < 4; j++) sacc[i][j] = 0.f;

#pragma unroll 8
        for (int k = 0; k < 128; k++) {
            int sw = (k >> 2) & 15;
            float4 aq = *(const float4*)&Qt[k*64 + ((ty ^ sw) << 2)];
            float4 bk = *(const float4*)&Kt[k*64 + ((tx ^ sw) << 2)];
            const float* ap = (const float*)&aq;
            const float* bp = (const float*)&bk;
#pragma unroll
            for (int i = 0; i < 4; i++)
#pragma unroll
                for (int j = 0; j < 4; j++)
                    sacc[i][j] = fmaf(ap[i], bp[j], sacc[i][j]);
        }
        const bool diag = (kt == qt);
#pragma unroll
        for (int i = 0; i < 4; i++)
#pragma unroll
            for (int j = 0; j < 4; j++) {
                float v = sacc[i][j] * SCALE;
                if (diag && (tx*4 + j) > (ty*4 + i)) v = NEG;
                Ss[(ty*4 + i)*68 + tx*4 + j] = v;
            }
        __syncthreads();

        // online softmax (4 threads per row)
        {
            int r = tid >> 2, sg = tid & 3;
            float* row = Ss + r*68 + sg*16;
            float mo = m_s[r];
            float mx = NEG;
#pragma unroll
            for (int c = 0; c < 16; c++) mx = fmaxf(mx, row[c]);
            mx = fmaxf(mx, __shfl_xor_sync(0xffffffffu, mx, 1));
            mx = fmaxf(mx, __shfl_xor_sync(0xffffffffu, mx, 2));
            float mn = fmaxf(mo, mx);
            float alpha = expf(mo - mn);
            float sum = 0.f;
#pragma unroll
            for (int c = 0; c < 16; c++) {
                float p = expf(row[c] - mn);
                row[c] = p;
                sum += p;
            }
            sum += __shfl_xor_sync(0xffffffffu, sum, 1);
            sum += __shfl_xor_sync(0xffffffffu, sum, 2);
            if (sg == 0) {
                m_s[r] = mn;
                l_s[r] = l_s[r] * alpha + sum;
                a_s[r] = alpha;
            }
        }
        __syncthreads();

        // rescale O, accumulate P*V
#pragma unroll
        for (int i = 0; i < 4; i++) {
            float al = a_s[ty*4 + i];
#pragma unroll
            for (int j = 0; j < 8; j++) oacc[i][j] *= al;
        }
#pragma unroll 4
        for (int j = 0; j < 64; j++) {
            float p0 = Ss[(ty*4 + 0)*68 + j];
            float p1 = Ss[(ty*4 + 1)*68 + j];
            float p2 = Ss[(ty*4 + 2)*68 + j];
            float p3 = Ss[(ty*4 + 3)*68 + j];
            float4 v0 = *(const float4*)&Vs[j*128 + tx*8];
            float4 v1 = *(const float4*)&Vs[j*128 + tx*8 + 4];
            const float* va = (const float*)&v0;
            const float* vb = (const float*)&v1;
#pragma unroll
            for (int c = 0; c < 4; c++) {
                oacc[0][c]   = fmaf(p0, va[c], oacc[0][c]);
                oacc[1][c]   = fmaf(p1, va[c], oacc[1][c]);
                oacc[2][c]   = fmaf(p2, va[c], oacc[2][c]);
                oacc[3][c]   = fmaf(p3, va[c], oacc[3][c]);
                oacc[0][4+c] = fmaf(p0, vb[c], oacc[0][4+c]);
                oacc[1][4+c] = fmaf(p1, vb[c], oacc[1][4+c]);
                oacc[2][4+c] = fmaf(p2, vb[c], oacc[2][4+c]);
                oacc[3][4+c] = fmaf(p3, vb[c], oacc[3][4+c]);
            }
        }
    }

    // epilogue: O / l, write
#pragma unroll
    for (int i = 0; i < 4; i++) {
        float inv = 1.f / l_s[ty*4 + i];
        float* op = O + (rowbase + qi0 + ty*4 + i) * Dm + hoff + tx*8;
        *(float4*)op     = make_float4(oacc[i][0]*inv, oacc[i][1]*inv,
                                       oacc[i][2]*inv, oacc[i][3]*inv);
        *(float4*)(op+4) = make_float4(oacc[i][4]*inv, oacc[i][5]*inv,
                                       oacc[i][6]*inv, oacc[i][7]*inv);
    }
}

// ---------------- launch ------------------------------------------------------
extern "C" void kernel_launch(void* const* d_in, const int* in_sizes, int n_in,
                              void* d_out, int out_size)
{
    const float* x  = (const float*)d_in[0];
    const int*  pos = (const int*)d_in[1];
    const float* Wq = (const float*)d_in[2];
    const float* Wk = (const float*)d_in[3];
    const float* Wv = (const float*)d_in[4];
    const float* Wo = (const float*)d_in[5];
    float* out = (float*)d_out;

    float *qp, *kp, *vp, *op;
    cudaGetSymbolAddress((void**)&qp, g_Q);
    cudaGetSymbolAddress((void**)&kp, g_K);
    cudaGetSymbolAddress((void**)&vp, g_V);
    cudaGetSymbolAddress((void**)&op, g_O);

    invf_kernel<<<1, 64>>>();

    dim3 gblk(Dm/128, Mm/128);   // (16, 32)
    sgemm_nt<<<gblk, 256>>>(x, Wq, qp, Dm, Dm);
    sgemm_nt<<<gblk, 256>>>(x, Wk, kp, Dm, Dm);
    sgemm_nt<<<gblk, 256>>>(x, Wv, vp, Dm, Dm);

    int npairs = Bb * Ll * Hn * (Dh/2);
    rope_kernel<<<npairs/256, 256>>>(pos, qp, kp);

    cudaFuncSetAttribute(attn_kernel,
                         cudaFuncAttributeMaxDynamicSharedMemorySize,
                         ATT_SMEM_FLOATS * (int)sizeof(float));
    dim3 agrid(Ll/64, Hn, Bb);
    attn_kernel<<<agrid, 256, ATT_SMEM_FLOATS * (int)sizeof(float)>>>(qp, kp, vp, op);

    sgemm_nt<<<gblk, 256>>>(op, Wo, out, Dm, Dm);
}